// round 3
// baseline (speedup 1.0000x reference)
#include <cuda_runtime.h>
#include <cuda_bf16.h>
#include <cstdint>

// Problem dims
#define BB 8
#define SS 2048
#define DIN 1024
#define DOUT 64
#define ROWS_TOTAL (BB * SS)   // 16384

typedef unsigned long long ull;

// Scratch for projected q/k/v  (3 x 4 MB device globals; no allocs allowed)
__device__ float g_q[ROWS_TOTAL * DOUT];
__device__ float g_k[ROWS_TOTAL * DOUT];
__device__ float g_v[ROWS_TOTAL * DOUT];

// Mask dtype flag: 0 = uint8/bool, 1 = int32, 2 = float32
__device__ int g_mask_kind;

// ---------------------------------------------------------------------------
// packed f32x2 helpers (sm_103a FFMA2 — only reachable via explicit PTX)
// ---------------------------------------------------------------------------
static __device__ __forceinline__ ull pk2(float lo, float hi) {
    ull r;
    asm("mov.b64 %0, {%1,%2};" : "=l"(r)
        : "r"(__float_as_uint(lo)), "r"(__float_as_uint(hi)));
    return r;
}
static __device__ __forceinline__ float2 upk2(ull v) {
    unsigned int lo, hi;
    asm("mov.b64 {%0,%1}, %2;" : "=r"(lo), "=r"(hi) : "l"(v));
    return make_float2(__uint_as_float(lo), __uint_as_float(hi));
}
static __device__ __forceinline__ ull ffma2(ull a, ull b, ull c) {
    ull d;
    asm("fma.rn.f32x2 %0, %1, %2, %3;" : "=l"(d) : "l"(a), "l"(b), "l"(c));
    return d;
}
static __device__ __forceinline__ ull fmul2(ull a, ull b) {
    ull d;
    asm("mul.rn.f32x2 %0, %1, %2;" : "=l"(d) : "l"(a), "l"(b));
    return d;
}

// ---------------------------------------------------------------------------
// Kernel 0: sniff the mask buffer's element dtype (first 2048 words = 8 KB).
//   f32 bool: nonzero words are exactly 0x3F800000
//   u8  bool: some word has a byte set above byte 0
//   i32 bool: every word is 0 or 1
// ---------------------------------------------------------------------------
__global__ void detect_mask_kernel(const unsigned int* __restrict__ m)
{
    __shared__ int sawF, sawHigh;
    if (threadIdx.x == 0) { sawF = 0; sawHigh = 0; }
    __syncthreads();
    for (int i = threadIdx.x; i < 2048; i += 256) {
        unsigned int w = m[i];
        if (w == 0x3F800000u) sawF = 1;
        else if (w & 0xFFFFFF00u) sawHigh = 1;
    }
    __syncthreads();
    if (threadIdx.x == 0)
        g_mask_kind = sawF ? 2 : (sawHigh ? 0 : 1);
}

// ---------------------------------------------------------------------------
// Kernel 1: fused QKV projection with packed f32x2 FMA.
// Tile 64x64, K-step 16, 256 threads, 4x4 micro-tile (2 packed pairs / row).
// ---------------------------------------------------------------------------
__global__ __launch_bounds__(256) void qkv_kernel(
    const float* __restrict__ seq,
    const float* __restrict__ Wq, const float* __restrict__ bq,
    const float* __restrict__ Wk, const float* __restrict__ bk,
    const float* __restrict__ Wv, const float* __restrict__ bv)
{
    __shared__ float As[16][68];   // [kk][m]
    __shared__ float Bs[16][68];   // [kk][n]

    const float* W;
    const float* bias;
    float* out;
    if (blockIdx.y == 0)      { W = Wq; bias = bq; out = g_q; }
    else if (blockIdx.y == 1) { W = Wk; bias = bk; out = g_k; }
    else                      { W = Wv; bias = bv; out = g_v; }

    const int row0 = blockIdx.x * 64;
    const int tid  = threadIdx.x;
    const int ty   = tid >> 4;      // 0..15
    const int tx   = tid & 15;      // 0..15

    ull c2[4][2];
#pragma unroll
    for (int i = 0; i < 4; i++) { c2[i][0] = 0ull; c2[i][1] = 0ull; }

    for (int k0 = 0; k0 < DIN; k0 += 16) {
#pragma unroll
        for (int i = 0; i < 4; i++) {
            int e    = tid + i * 256;      // e = m*16 + kk
            int mrow = e >> 4;
            int kk   = e & 15;
            As[kk][mrow] = seq[(size_t)(row0 + mrow) * DIN + k0 + kk];
            int kk2 = e >> 6;              // e = kk*64 + n
            int nn  = e & 63;
            Bs[kk2][nn] = W[(size_t)(k0 + kk2) * DOUT + nn];
        }
        __syncthreads();

#pragma unroll
        for (int kk = 0; kk < 16; kk++) {
            float4 a = *(const float4*)&As[kk][ty * 4];
            ulonglong2 bb = *(const ulonglong2*)&Bs[kk][tx * 4];
            ull a0 = pk2(a.x, a.x), a1 = pk2(a.y, a.y);
            ull a2 = pk2(a.z, a.z), a3 = pk2(a.w, a.w);
            c2[0][0] = ffma2(a0, bb.x, c2[0][0]);
            c2[0][1] = ffma2(a0, bb.y, c2[0][1]);
            c2[1][0] = ffma2(a1, bb.x, c2[1][0]);
            c2[1][1] = ffma2(a1, bb.y, c2[1][1]);
            c2[2][0] = ffma2(a2, bb.x, c2[2][0]);
            c2[2][1] = ffma2(a2, bb.y, c2[2][1]);
            c2[3][0] = ffma2(a3, bb.x, c2[3][0]);
            c2[3][1] = ffma2(a3, bb.y, c2[3][1]);
        }
        __syncthreads();
    }

    float bj[4];
#pragma unroll
    for (int j = 0; j < 4; j++) bj[j] = bias[tx * 4 + j];

#pragma unroll
    for (int i = 0; i < 4; i++) {
        float2 p0 = upk2(c2[i][0]);
        float2 p1 = upk2(c2[i][1]);
        float4 r;
        r.x = p0.x + bj[0];
        r.y = p0.y + bj[1];
        r.z = p1.x + bj[2];
        r.w = p1.y + bj[3];
        *(float4*)&out[(size_t)(row0 + ty * 4 + i) * DOUT + tx * 4] = r;
    }
}

// ---------------------------------------------------------------------------
// Kernel 2: flash-attention, fp32 with packed f32x2 FMA.
// One block = (batch b, 64-query tile). 256 threads (16x16), 4x4 micro-tiles.
// scale = 1/sqrt(S)  (reference scales by sqrt(q.shape[1]) == sqrt(S)).
// ---------------------------------------------------------------------------
__global__ __launch_bounds__(256) void attn_kernel(
    const void* __restrict__ mask_raw,
    float* __restrict__ out)
{
    extern __shared__ float sm[];
    float (*Qs)[68] = (float (*)[68])(sm);                 // [d][q]
    float (*Ks)[68] = (float (*)[68])(sm + 64 * 68);       // [d][k]
    float (*Vs)[68] = (float (*)[68])(sm + 2 * 64 * 68);   // [k][d]
    float (*Ps)[68] = (float (*)[68])(sm + 3 * 64 * 68);   // [k][q]
    float* Mflag    = sm + 4 * 64 * 68;                    // [64]

    const int b   = blockIdx.y;
    const int q0  = blockIdx.x * 64;
    const int tid = threadIdx.x;
    const int ty  = tid >> 4;   // query group
    const int tx  = tid & 15;   // key / dim group

    const float inv_scale = rsqrtf((float)SS);
    const int   mask_kind = g_mask_kind;

    // fill-helper indices: conflict-free transposed stores
    const int frow = tid & 63;       // source row (query or key index)
    const int dgrp = tid >> 6;       // 0..3

    // Load Q tile transposed: Qs[d][q]  (float4 gmem loads, cf scalar stores)
    {
        const float* qptr = g_q + (size_t)(b * SS + q0) * DOUT;
#pragma unroll
        for (int i = 0; i < 4; i++) {
            int dd4 = dgrp * 4 + i * 16;
            float4 t = *(const float4*)&qptr[frow * 64 + dd4];
            Qs[dd4 + 0][frow] = t.x;
            Qs[dd4 + 1][frow] = t.y;
            Qs[dd4 + 2][frow] = t.z;
            Qs[dd4 + 3][frow] = t.w;
        }
    }

    ull o2[4][2];
    float m[4], l[4];
#pragma unroll
    for (int i = 0; i < 4; i++) {
        m[i] = -1e9f;
        l[i] = 0.0f;
        o2[i][0] = 0ull;
        o2[i][1] = 0ull;
    }

    for (int k0 = 0; k0 < SS; k0 += 64) {
        __syncthreads();   // protect Ks/Vs/Ps (and first-iter Qs) from prior readers

        const float* kptr = g_k + (size_t)(b * SS + k0) * DOUT;
        const float* vptr = g_v + (size_t)(b * SS + k0) * DOUT;

        // K transposed: float4 loads, conflict-free scalar stores
#pragma unroll
        for (int i = 0; i < 4; i++) {
            int dd4 = dgrp * 4 + i * 16;
            float4 t = *(const float4*)&kptr[frow * 64 + dd4];
            Ks[dd4 + 0][frow] = t.x;
            Ks[dd4 + 1][frow] = t.y;
            Ks[dd4 + 2][frow] = t.z;
            Ks[dd4 + 3][frow] = t.w;
        }
        // V natural: vectorized copy
#pragma unroll
        for (int i = 0; i < 4; i++) {
            int f    = tid + i * 256;   // float4 index: row*16 + c4
            int vrow = f >> 4;
            int c4   = f & 15;
            *(float4*)&Vs[vrow][c4 * 4] =
                *(const float4*)&vptr[vrow * 64 + c4 * 4];
        }
        if (tid < 64) {
            int idx = b * SS + k0 + tid;
            bool mk;
            if (mask_kind == 2)      mk = ((const float*)mask_raw)[idx] != 0.0f;
            else if (mask_kind == 1) mk = ((const int*)mask_raw)[idx] != 0;
            else                     mk = ((const unsigned char*)mask_raw)[idx] != 0;
            Mflag[tid] = mk ? 1.0f : 0.0f;
        }
        __syncthreads();

        // --- scores GEMM (packed): s[q][k] = sum_d Q[q][d] * K[k][d] ---
        ull s2[4][2];
#pragma unroll
        for (int i = 0; i < 4; i++) { s2[i][0] = 0ull; s2[i][1] = 0ull; }

#pragma unroll 8
        for (int dd = 0; dd < 64; dd++) {
            float4 a = *(const float4*)&Qs[dd][ty * 4];
            ulonglong2 bb = *(const ulonglong2*)&Ks[dd][tx * 4];
            ull a0 = pk2(a.x, a.x), a1 = pk2(a.y, a.y);
            ull a2 = pk2(a.z, a.z), a3 = pk2(a.w, a.w);
            s2[0][0] = ffma2(a0, bb.x, s2[0][0]);
            s2[0][1] = ffma2(a0, bb.y, s2[0][1]);
            s2[1][0] = ffma2(a1, bb.x, s2[1][0]);
            s2[1][1] = ffma2(a1, bb.y, s2[1][1]);
            s2[2][0] = ffma2(a2, bb.x, s2[2][0]);
            s2[2][1] = ffma2(a2, bb.y, s2[2][1]);
            s2[3][0] = ffma2(a3, bb.x, s2[3][0]);
            s2[3][1] = ffma2(a3, bb.y, s2[3][1]);
        }

        // unpack, scale + mask
        float s[4][4];
        float mf[4];
#pragma unroll
        for (int j = 0; j < 4; j++) mf[j] = Mflag[tx * 4 + j];
#pragma unroll
        for (int i = 0; i < 4; i++) {
            float2 p0 = upk2(s2[i][0]);
            float2 p1 = upk2(s2[i][1]);
            s[i][0] = (mf[0] != 0.0f) ? -1e9f : p0.x * inv_scale;
            s[i][1] = (mf[1] != 0.0f) ? -1e9f : p0.y * inv_scale;
            s[i][2] = (mf[2] != 0.0f) ? -1e9f : p1.x * inv_scale;
            s[i][3] = (mf[3] != 0.0f) ? -1e9f : p1.y * inv_scale;
        }

        // --- online softmax per query row (row spread over 16 tx lanes) ---
#pragma unroll
        for (int i = 0; i < 4; i++) {
            float rmax = fmaxf(fmaxf(s[i][0], s[i][1]), fmaxf(s[i][2], s[i][3]));
#pragma unroll
            for (int off = 8; off >= 1; off >>= 1)
                rmax = fmaxf(rmax, __shfl_xor_sync(0xffffffffu, rmax, off, 16));
            float mn    = fmaxf(m[i], rmax);
            float alpha = __expf(m[i] - mn);
            float rs = 0.0f;
#pragma unroll
            for (int j = 0; j < 4; j++) {
                float p = __expf(s[i][j] - mn);
                s[i][j] = p;
                rs += p;
            }
#pragma unroll
            for (int off = 8; off >= 1; off >>= 1)
                rs += __shfl_xor_sync(0xffffffffu, rs, off, 16);
            l[i] = l[i] * alpha + rs;
            m[i] = mn;
            ull a2d = pk2(alpha, alpha);
            o2[i][0] = fmul2(a2d, o2[i][0]);
            o2[i][1] = fmul2(a2d, o2[i][1]);
        }

        // store P transposed: Ps[k][q] — vectorized over q (float4 per j)
#pragma unroll
        for (int j = 0; j < 4; j++) {
            float4 p;
            p.x = s[0][j];
            p.y = s[1][j];
            p.z = s[2][j];
            p.w = s[3][j];
            *(float4*)&Ps[tx * 4 + j][ty * 4] = p;
        }
        __syncthreads();

        // --- PV GEMM (packed): o[q][d] += sum_k P[q][k] * V[k][d] ---
#pragma unroll 8
        for (int kk = 0; kk < 64; kk++) {
            float4 a = *(const float4*)&Ps[kk][ty * 4];
            ulonglong2 vv = *(const ulonglong2*)&Vs[kk][tx * 4];
            ull a0 = pk2(a.x, a.x), a1 = pk2(a.y, a.y);
            ull a2 = pk2(a.z, a.z), a3 = pk2(a.w, a.w);
            o2[0][0] = ffma2(a0, vv.x, o2[0][0]);
            o2[0][1] = ffma2(a0, vv.y, o2[0][1]);
            o2[1][0] = ffma2(a1, vv.x, o2[1][0]);
            o2[1][1] = ffma2(a1, vv.y, o2[1][1]);
            o2[2][0] = ffma2(a2, vv.x, o2[2][0]);
            o2[2][1] = ffma2(a2, vv.y, o2[2][1]);
            o2[3][0] = ffma2(a3, vv.x, o2[3][0]);
            o2[3][1] = ffma2(a3, vv.y, o2[3][1]);
        }
    }

    // epilogue: divide by l, write out
#pragma unroll
    for (int i = 0; i < 4; i++) {
        float invl = 1.0f / l[i];
        float2 p0 = upk2(o2[i][0]);
        float2 p1 = upk2(o2[i][1]);
        float4 r;
        r.x = p0.x * invl;
        r.y = p0.y * invl;
        r.z = p1.x * invl;
        r.w = p1.y * invl;
        *(float4*)&out[((size_t)(b * SS) + q0 + ty * 4 + i) * DOUT + tx * 4] = r;
    }
}

// ---------------------------------------------------------------------------
extern "C" void kernel_launch(void* const* d_in, const int* in_sizes, int n_in,
                              void* d_out, int out_size)
{
    const float* seq  = (const float*)d_in[0];
    const void*  mask = d_in[1];
    const float* Wq   = (const float*)d_in[2];
    const float* bq   = (const float*)d_in[3];
    const float* Wk   = (const float*)d_in[4];
    const float* bk   = (const float*)d_in[5];
    const float* Wv   = (const float*)d_in[6];
    const float* bv   = (const float*)d_in[7];
    float* out = (float*)d_out;

    const int attn_smem = (4 * 64 * 68 + 64) * (int)sizeof(float);
    cudaFuncSetAttribute(attn_kernel,
                         cudaFuncAttributeMaxDynamicSharedMemorySize,
                         attn_smem);

    detect_mask_kernel<<<1, 256>>>((const unsigned int*)mask);
    qkv_kernel<<<dim3(ROWS_TOTAL / 64, 3), 256>>>(seq, Wq, bq, Wk, bk, Wv, bv);
    attn_kernel<<<dim3(SS / 64, BB), 256, attn_smem>>>(mask, out);
}

// round 6
// speedup vs baseline: 1.9347x; 1.9347x over previous
#include <cuda_runtime.h>
#include <cuda_bf16.h>
#include <cstdint>

// Problem dims
#define BB 8
#define SS 2048
#define DIN 1024
#define DOUT 64
#define ROWS_TOTAL (BB * SS)   // 16384
#define AP 72                  // padded bf16 row length (144 B) -> conflict-free ldmatrix

// Scratch for projected q/k/v (3 x 4 MB device globals; no allocs allowed)
__device__ float g_q[ROWS_TOTAL * DOUT];
__device__ float g_k[ROWS_TOTAL * DOUT];
__device__ float g_v[ROWS_TOTAL * DOUT];

// Pre-split, transposed weights: [w][kb][n][k_local] (kb = k/64)
__device__ __nv_bfloat16 g_Wh[3 * 16 * 64 * 64];
__device__ __nv_bfloat16 g_Wm[3 * 16 * 64 * 64];

// Mask dtype flag: 0 = uint8/bool, 1 = int32, 2 = float32
__device__ int g_mask_kind;

// ---------------------------------------------------------------------------
// helpers
// ---------------------------------------------------------------------------
static __device__ __forceinline__ uint32_t smem_u32(const void* p) {
    uint32_t a;
    asm("{ .reg .u64 t; cvta.to.shared.u64 t, %1; cvt.u32.u64 %0, t; }"
        : "=r"(a) : "l"(p));
    return a;
}
static __device__ __forceinline__ void ldsm_x4(uint32_t* r, uint32_t addr) {
    asm volatile("ldmatrix.sync.aligned.m8n8.x4.shared.b16 {%0,%1,%2,%3}, [%4];"
                 : "=r"(r[0]), "=r"(r[1]), "=r"(r[2]), "=r"(r[3]) : "r"(addr));
}
static __device__ __forceinline__ void ldsm_x2(uint32_t* r, uint32_t addr) {
    asm volatile("ldmatrix.sync.aligned.m8n8.x2.shared.b16 {%0,%1}, [%2];"
                 : "=r"(r[0]), "=r"(r[1]) : "r"(addr));
}
static __device__ __forceinline__ void mma16816(float* c, const uint32_t* a,
                                                const uint32_t* b) {
    asm volatile(
        "mma.sync.aligned.m16n8k16.row.col.f32.bf16.bf16.f32 "
        "{%0,%1,%2,%3}, {%4,%5,%6,%7}, {%8,%9}, {%0,%1,%2,%3};"
        : "+f"(c[0]), "+f"(c[1]), "+f"(c[2]), "+f"(c[3])
        : "r"(a[0]), "r"(a[1]), "r"(a[2]), "r"(a[3]), "r"(b[0]), "r"(b[1]));
}
static __device__ __forceinline__ void split2(float x, float y,
                                              uint32_t& hi, uint32_t& mid) {
    __nv_bfloat162 h = __floats2bfloat162_rn(x, y);
    __nv_bfloat162 m = __floats2bfloat162_rn(x - __bfloat162float(h.x),
                                             y - __bfloat162float(h.y));
    hi  = *(uint32_t*)&h;
    mid = *(uint32_t*)&m;
}

// ---------------------------------------------------------------------------
// Kernel 0: sniff mask dtype (first 2048 words = 8 KB).
// ---------------------------------------------------------------------------
__global__ void detect_mask_kernel(const unsigned int* __restrict__ m)
{
    __shared__ int sawF, sawHigh;
    if (threadIdx.x == 0) { sawF = 0; sawHigh = 0; }
    __syncthreads();
    for (int i = threadIdx.x; i < 2048; i += 256) {
        unsigned int w = m[i];
        if (w == 0x3F800000u) sawF = 1;
        else if (w & 0xFFFFFF00u) sawHigh = 1;
    }
    __syncthreads();
    if (threadIdx.x == 0)
        g_mask_kind = sawF ? 2 : (sawHigh ? 0 : 1);
}

// ---------------------------------------------------------------------------
// Kernel P: split weights to bf16 hi/mid, transpose to [n][k] per K-block.
// ---------------------------------------------------------------------------
__global__ void prep_w_kernel(const float* __restrict__ Wq,
                              const float* __restrict__ Wk,
                              const float* __restrict__ Wv)
{
    int w = blockIdx.y;
    const float* W = (w == 0) ? Wq : (w == 1) ? Wk : Wv;
    int e = blockIdx.x * 256 + threadIdx.x;   // over [k][n]
    float x = W[e];
    int k = e >> 6, n = e & 63;
    __nv_bfloat16 hi = __float2bfloat16_rn(x);
    __nv_bfloat16 mid = __float2bfloat16_rn(x - __bfloat162float(hi));
    int o = w * 65536 + (k >> 6) * 4096 + n * 64 + (k & 63);
    g_Wh[o] = hi;
    g_Wm[o] = mid;
}

// ---------------------------------------------------------------------------
// Kernel 1: QKV projection via mma.sync bf16 3-MMA split.
// CTA = 128 rows; 8 warps (4m x 2n); all three weights in one pass.
// ---------------------------------------------------------------------------
__global__ __launch_bounds__(256) void qkv_mma_kernel(
    const float* __restrict__ seq,
    const float* __restrict__ bq,
    const float* __restrict__ bk,
    const float* __restrict__ bv)
{
    extern __shared__ char smc[];
    __nv_bfloat16* Ah = (__nv_bfloat16*)smc;            // 128 x AP
    __nv_bfloat16* Am = Ah + 128 * AP;
    __nv_bfloat16* Bh = Am + 128 * AP;                  // 3 x 64 x AP
    __nv_bfloat16* Bm = Bh + 3 * 64 * AP;

    const int tid  = threadIdx.x;
    const int wid  = tid >> 5, lane = tid & 31;
    const int wm   = wid >> 1, wn = wid & 1;
    const int row0 = blockIdx.x * 128;
    const uint32_t sb  = smem_u32(smc);
    const uint32_t AhB = sb;
    const uint32_t AmB = sb + 128 * AP * 2;
    const uint32_t BhB = AmB + 128 * AP * 2;
    const uint32_t BmB = BhB + 3 * 64 * AP * 2;

    float cc[3][2][4][4];
#pragma unroll
    for (int w = 0; w < 3; w++)
#pragma unroll
        for (int mi = 0; mi < 2; mi++)
#pragma unroll
            for (int ni = 0; ni < 4; ni++)
#pragma unroll
                for (int r = 0; r < 4; r++) cc[w][mi][ni][r] = 0.0f;

    for (int kb = 0; kb < 16; kb++) {
        __syncthreads();
        // A fill: 128 x 64 fp32 -> hi/mid
#pragma unroll
        for (int it = 0; it < 8; it++) {
            int f   = tid + it * 256;
            int row = f >> 4, k4 = f & 15;
            float4 t = *(const float4*)&seq[(size_t)(row0 + row) * DIN + kb * 64 + k4 * 4];
            uint32_t h0, m0, h1, m1;
            split2(t.x, t.y, h0, m0);
            split2(t.z, t.w, h1, m1);
            int off = row * AP + k4 * 4;
            *(uint32_t*)(Ah + off)     = h0;
            *(uint32_t*)(Ah + off + 2) = h1;
            *(uint32_t*)(Am + off)     = m0;
            *(uint32_t*)(Am + off + 2) = m1;
        }
        // B fill: prepped weights, straight uint4 copies
        {
            const uint4* wh4 = (const uint4*)g_Wh;
            const uint4* wm4 = (const uint4*)g_Wm;
#pragma unroll
            for (int it = 0; it < 12; it++) {
                int u  = tid + it * 256;          // 0..3071
                int sp = (u >= 1536);
                int u2 = u - sp * 1536;           // FIX: 1536 is not pow2; no AND trick
                int w  = u2 >> 9;
                int r  = u2 & 511;
                int n  = r >> 3, ch = r & 7;
                uint4 val = (sp ? wm4 : wh4)[w * 8192 + kb * 512 + n * 8 + ch];
                __nv_bfloat16* dst = (sp ? Bm : Bh) + w * 64 * AP + n * AP + ch * 8;
                *(uint4*)dst = val;
            }
        }
        __syncthreads();

#pragma unroll
        for (int ks = 0; ks < 4; ks++) {
            const int k0 = ks * 16;
            uint32_t ah[2][4], am[2][4];
#pragma unroll
            for (int mi = 0; mi < 2; mi++) {
                uint32_t r = wm * 32 + mi * 16 + (lane & 15);
                uint32_t c = k0 + (lane >> 4) * 8;
                ldsm_x4(ah[mi], AhB + (r * AP + c) * 2);
                ldsm_x4(am[mi], AmB + (r * AP + c) * 2);
            }
#pragma unroll
            for (int w = 0; w < 3; w++) {
                const uint32_t base = w * 64 * AP * 2;
                uint32_t bh[4][2], bm[4][2];
#pragma unroll
                for (int ni = 0; ni < 4; ni++) {
                    uint32_t nr = wn * 32 + ni * 8 + (lane & 7);
                    uint32_t c  = k0 + ((lane >> 3) & 1) * 8;
                    ldsm_x2(bh[ni], BhB + base + (nr * AP + c) * 2);
                    ldsm_x2(bm[ni], BmB + base + (nr * AP + c) * 2);
                }
#pragma unroll
                for (int mi = 0; mi < 2; mi++)
#pragma unroll
                    for (int ni = 0; ni < 4; ni++) {
                        mma16816(cc[w][mi][ni], ah[mi], bh[ni]);
                        mma16816(cc[w][mi][ni], ah[mi], bm[ni]);
                        mma16816(cc[w][mi][ni], am[mi], bh[ni]);
                    }
            }
        }
    }

    // epilogue
    const int g = lane >> 2, t4 = lane & 3;
#pragma unroll
    for (int w = 0; w < 3; w++) {
        const float* bias = (w == 0) ? bq : (w == 1) ? bk : bv;
        float* outp = (w == 0) ? g_q : (w == 1) ? g_k : g_v;
#pragma unroll
        for (int mi = 0; mi < 2; mi++)
#pragma unroll
            for (int ni = 0; ni < 4; ni++) {
                int row = row0 + wm * 32 + mi * 16 + g;
                int col = wn * 32 + ni * 8 + t4 * 2;
                float bx = bias[col], by = bias[col + 1];
                float2 r0 = make_float2(cc[w][mi][ni][0] + bx, cc[w][mi][ni][1] + by);
                float2 r1 = make_float2(cc[w][mi][ni][2] + bx, cc[w][mi][ni][3] + by);
                *(float2*)&outp[(size_t)row * 64 + col]       = r0;
                *(float2*)&outp[(size_t)(row + 8) * 64 + col] = r1;
            }
    }
}

// ---------------------------------------------------------------------------
// Kernel 2: flash-attention with mma.sync bf16 split GEMMs + SIMT softmax.
// Block = (batch b, 64-query tile), 256 threads, 8 warps (2m x 4n).
// ---------------------------------------------------------------------------
#define OFF_QH  0
#define OFF_QM  (OFF_QH + 64 * AP * 2)
#define OFF_KH  (OFF_QM + 64 * AP * 2)
#define OFF_KM  (OFF_KH + 64 * AP * 2)
#define OFF_VTH (OFF_KM + 64 * AP * 2)
#define OFF_VTM (OFF_VTH + 64 * AP * 2)
#define OFF_PH  (OFF_VTM + 64 * AP * 2)
#define OFF_PM  (OFF_PH + 64 * AP * 2)
#define OFF_SS  (OFF_PM + 64 * AP * 2)          // 64 x 68 fp32
#define OFF_MF  (OFF_SS + 64 * 68 * 4)
#define OFF_MR  (OFF_MF + 64 * 4)
#define OFF_LR  (OFF_MR + 64 * 4)
#define OFF_AL  (OFF_LR + 64 * 4)
#define ATTN_SMEM (OFF_AL + 64 * 4)

__global__ __launch_bounds__(256) void attn_mma_kernel(
    const void* __restrict__ mask_raw,
    float* __restrict__ out)
{
    extern __shared__ char smc[];
    __nv_bfloat16* Qh  = (__nv_bfloat16*)(smc + OFF_QH);
    __nv_bfloat16* Qm  = (__nv_bfloat16*)(smc + OFF_QM);
    __nv_bfloat16* Kh  = (__nv_bfloat16*)(smc + OFF_KH);
    __nv_bfloat16* Km  = (__nv_bfloat16*)(smc + OFF_KM);
    __nv_bfloat16* Vth = (__nv_bfloat16*)(smc + OFF_VTH);
    __nv_bfloat16* Vtm = (__nv_bfloat16*)(smc + OFF_VTM);
    __nv_bfloat16* Ph  = (__nv_bfloat16*)(smc + OFF_PH);
    __nv_bfloat16* Pm  = (__nv_bfloat16*)(smc + OFF_PM);
    float* Ss   = (float*)(smc + OFF_SS);
    float* Mf   = (float*)(smc + OFF_MF);
    float* Mrow = (float*)(smc + OFF_MR);
    float* Lrow = (float*)(smc + OFF_LR);
    float* Al   = (float*)(smc + OFF_AL);

    const int b   = blockIdx.y;
    const int q0  = blockIdx.x * 64;
    const int tid = threadIdx.x;
    const int wid = tid >> 5, lane = tid & 31;
    const int wm  = wid & 1, wn = wid >> 1;      // 2m x 4n
    const int g   = lane >> 2, t4 = lane & 3;
    const uint32_t sb = smem_u32(smc);
    const float inv_scale = rsqrtf((float)SS);
    const int   mask_kind = g_mask_kind;

    // Q fill (once): 64 x 64 fp32 -> hi/mid
#pragma unroll
    for (int it = 0; it < 4; it++) {
        int f   = tid + it * 256;
        int row = f >> 4, k4 = f & 15;
        float4 t = *(const float4*)&g_q[(size_t)(b * SS + q0 + row) * 64 + k4 * 4];
        uint32_t h0, m0, h1, m1;
        split2(t.x, t.y, h0, m0);
        split2(t.z, t.w, h1, m1);
        int off = row * AP + k4 * 4;
        *(uint32_t*)(Qh + off)     = h0;
        *(uint32_t*)(Qh + off + 2) = h1;
        *(uint32_t*)(Qm + off)     = m0;
        *(uint32_t*)(Qm + off + 2) = m1;
    }
    if (tid < 64) { Mrow[tid] = -1e30f; Lrow[tid] = 0.0f; }

    float ov[2][2][4];
#pragma unroll
    for (int mi = 0; mi < 2; mi++)
#pragma unroll
        for (int ni = 0; ni < 2; ni++)
#pragma unroll
            for (int r = 0; r < 4; r++) ov[mi][ni][r] = 0.0f;

    for (int kt = 0; kt < 32; kt++) {
        const int kg = kt * 64;
        __syncthreads();   // protect K/V/P from previous readers

        // K fill (64 x 64)
#pragma unroll
        for (int it = 0; it < 4; it++) {
            int f   = tid + it * 256;
            int row = f >> 4, k4 = f & 15;
            float4 t = *(const float4*)&g_k[(size_t)(b * SS + kg + row) * 64 + k4 * 4];
            uint32_t h0, m0, h1, m1;
            split2(t.x, t.y, h0, m0);
            split2(t.z, t.w, h1, m1);
            int off = row * AP + k4 * 4;
            *(uint32_t*)(Kh + off)     = h0;
            *(uint32_t*)(Kh + off + 2) = h1;
            *(uint32_t*)(Km + off)     = m0;
            *(uint32_t*)(Km + off + 2) = m1;
        }
        // V transpose fill: Vt[d][kk]
#pragma unroll
        for (int it = 0; it < 4; it++) {
            int f  = tid + it * 256;
            int kk = f >> 4, d4 = f & 15;
            float4 t = *(const float4*)&g_v[(size_t)(b * SS + kg + kk) * 64 + d4 * 4];
            const float tv[4] = {t.x, t.y, t.z, t.w};
#pragma unroll
            for (int j = 0; j < 4; j++) {
                float x = tv[j];
                __nv_bfloat16 h = __float2bfloat16_rn(x);
                Vth[(d4 * 4 + j) * AP + kk] = h;
                Vtm[(d4 * 4 + j) * AP + kk] =
                    __float2bfloat16_rn(x - __bfloat162float(h));
            }
        }
        if (tid < 64) {
            int idx = b * SS + kg + tid;
            bool mk;
            if (mask_kind == 2)      mk = ((const float*)mask_raw)[idx] != 0.0f;
            else if (mask_kind == 1) mk = ((const int*)mask_raw)[idx] != 0;
            else                     mk = ((const unsigned char*)mask_raw)[idx] != 0;
            Mf[tid] = mk ? 1.0f : 0.0f;
        }
        __syncthreads();

        // ---- QK^T (3-MMA split) ----
        float sqk[2][2][4];
#pragma unroll
        for (int mi = 0; mi < 2; mi++)
#pragma unroll
            for (int ni = 0; ni < 2; ni++)
#pragma unroll
                for (int r = 0; r < 4; r++) sqk[mi][ni][r] = 0.0f;

#pragma unroll
        for (int ks = 0; ks < 4; ks++) {
            const int k0 = ks * 16;
            uint32_t qh[2][4], qm[2][4], kh[2][2], km2[2][2];
#pragma unroll
            for (int mi = 0; mi < 2; mi++) {
                uint32_t r = wm * 32 + mi * 16 + (lane & 15);
                uint32_t c = k0 + (lane >> 4) * 8;
                ldsm_x4(qh[mi], sb + OFF_QH + (r * AP + c) * 2);
                ldsm_x4(qm[mi], sb + OFF_QM + (r * AP + c) * 2);
            }
#pragma unroll
            for (int ni = 0; ni < 2; ni++) {
                uint32_t nr = wn * 16 + ni * 8 + (lane & 7);
                uint32_t c  = k0 + ((lane >> 3) & 1) * 8;
                ldsm_x2(kh[ni],  sb + OFF_KH + (nr * AP + c) * 2);
                ldsm_x2(km2[ni], sb + OFF_KM + (nr * AP + c) * 2);
            }
#pragma unroll
            for (int mi = 0; mi < 2; mi++)
#pragma unroll
                for (int ni = 0; ni < 2; ni++) {
                    mma16816(sqk[mi][ni], qh[mi], kh[ni]);
                    mma16816(sqk[mi][ni], qh[mi], km2[ni]);
                    mma16816(sqk[mi][ni], qm[mi], kh[ni]);
                }
        }
        // write raw scores to smem
#pragma unroll
        for (int mi = 0; mi < 2; mi++)
#pragma unroll
            for (int ni = 0; ni < 2; ni++) {
                int row = wm * 32 + mi * 16 + g;
                int col = wn * 16 + ni * 8 + t4 * 2;
                *(float2*)&Ss[row * 68 + col] =
                    make_float2(sqk[mi][ni][0], sqk[mi][ni][1]);
                *(float2*)&Ss[(row + 8) * 68 + col] =
                    make_float2(sqk[mi][ni][2], sqk[mi][ni][3]);
            }
        __syncthreads();

        // ---- SIMT online softmax: row r handled by 4 lanes ----
        {
            const int r  = tid >> 2;
            const int l4 = tid & 3;
            float sv[16];
            float rmax = -1e30f;
#pragma unroll
            for (int j = 0; j < 16; j++) {
                int c = l4 + j * 4;
                float s = Ss[r * 68 + c];
                s = (Mf[c] != 0.0f) ? -1e9f : s * inv_scale;
                sv[j] = s;
                rmax = fmaxf(rmax, s);
            }
            rmax = fmaxf(rmax, __shfl_xor_sync(0xffffffffu, rmax, 1, 4));
            rmax = fmaxf(rmax, __shfl_xor_sync(0xffffffffu, rmax, 2, 4));
            float mprev = Mrow[r];
            float mn    = fmaxf(mprev, rmax);
            float alpha = __expf(mprev - mn);
            float rs = 0.0f;
#pragma unroll
            for (int j = 0; j < 16; j++) {
                float p = __expf(sv[j] - mn);
                rs += p;
                int c = l4 + j * 4;
                __nv_bfloat16 h = __float2bfloat16_rn(p);
                Ph[r * AP + c] = h;
                Pm[r * AP + c] = __float2bfloat16_rn(p - __bfloat162float(h));
            }
            rs += __shfl_xor_sync(0xffffffffu, rs, 1, 4);
            rs += __shfl_xor_sync(0xffffffffu, rs, 2, 4);
            if (l4 == 0) {
                Mrow[r] = mn;
                Lrow[r] = Lrow[r] * alpha + rs;
                Al[r]   = alpha;
            }
        }
        __syncthreads();

        // ---- rescale O, then PV (3-MMA split) ----
#pragma unroll
        for (int mi = 0; mi < 2; mi++) {
            float ag  = Al[wm * 32 + mi * 16 + g];
            float ag8 = Al[wm * 32 + mi * 16 + g + 8];
#pragma unroll
            for (int ni = 0; ni < 2; ni++) {
                ov[mi][ni][0] *= ag;
                ov[mi][ni][1] *= ag;
                ov[mi][ni][2] *= ag8;
                ov[mi][ni][3] *= ag8;
            }
        }
#pragma unroll
        for (int ks = 0; ks < 4; ks++) {
            const int k0 = ks * 16;
            uint32_t ph[2][4], pm[2][4], vh[2][2], vm[2][2];
#pragma unroll
            for (int mi = 0; mi < 2; mi++) {
                uint32_t r = wm * 32 + mi * 16 + (lane & 15);
                uint32_t c = k0 + (lane >> 4) * 8;
                ldsm_x4(ph[mi], sb + OFF_PH + (r * AP + c) * 2);
                ldsm_x4(pm[mi], sb + OFF_PM + (r * AP + c) * 2);
            }
#pragma unroll
            for (int ni = 0; ni < 2; ni++) {
                uint32_t nr = wn * 16 + ni * 8 + (lane & 7);
                uint32_t c  = k0 + ((lane >> 3) & 1) * 8;
                ldsm_x2(vh[ni], sb + OFF_VTH + (nr * AP + c) * 2);
                ldsm_x2(vm[ni], sb + OFF_VTM + (nr * AP + c) * 2);
            }
#pragma unroll
            for (int mi = 0; mi < 2; mi++)
#pragma unroll
                for (int ni = 0; ni < 2; ni++) {
                    mma16816(ov[mi][ni], ph[mi], vh[ni]);
                    mma16816(ov[mi][ni], ph[mi], vm[ni]);
                    mma16816(ov[mi][ni], pm[mi], vh[ni]);
                }
        }
    }

    // ---- final: divide by l, write out ----
#pragma unroll
    for (int mi = 0; mi < 2; mi++) {
        int rbase = wm * 32 + mi * 16 + g;
        float il  = 1.0f / Lrow[rbase];
        float il8 = 1.0f / Lrow[rbase + 8];
#pragma unroll
        for (int ni = 0; ni < 2; ni++) {
            int col = wn * 16 + ni * 8 + t4 * 2;
            *(float2*)&out[((size_t)(b * SS) + q0 + rbase) * 64 + col] =
                make_float2(ov[mi][ni][0] * il, ov[mi][ni][1] * il);
            *(float2*)&out[((size_t)(b * SS) + q0 + rbase + 8) * 64 + col] =
                make_float2(ov[mi][ni][2] * il8, ov[mi][ni][3] * il8);
        }
    }
}

// ---------------------------------------------------------------------------
extern "C" void kernel_launch(void* const* d_in, const int* in_sizes, int n_in,
                              void* d_out, int out_size)
{
    const float* seq  = (const float*)d_in[0];
    const void*  mask = d_in[1];
    const float* Wq   = (const float*)d_in[2];
    const float* bq   = (const float*)d_in[3];
    const float* Wk   = (const float*)d_in[4];
    const float* bk   = (const float*)d_in[5];
    const float* Wv   = (const float*)d_in[6];
    const float* bv   = (const float*)d_in[7];
    float* out = (float*)d_out;

    const int qkv_smem  = (2 * 128 + 6 * 64) * AP * 2;   // 92160
    const int attn_smem = ATTN_SMEM;
    cudaFuncSetAttribute(qkv_mma_kernel,
                         cudaFuncAttributeMaxDynamicSharedMemorySize, qkv_smem);
    cudaFuncSetAttribute(attn_mma_kernel,
                         cudaFuncAttributeMaxDynamicSharedMemorySize, attn_smem);

    detect_mask_kernel<<<1, 256>>>((const unsigned int*)mask);
    prep_w_kernel<<<dim3(256, 3), 256>>>(Wq, Wk, Wv);
    qkv_mma_kernel<<<ROWS_TOTAL / 128, 256, qkv_smem>>>(seq, bq, bk, bv);
    attn_mma_kernel<<<dim3(SS / 64, BB), 256, attn_smem>>>(mask, out);
}

// round 7
// speedup vs baseline: 2.8126x; 1.4538x over previous
#include <cuda_runtime.h>
#include <cuda_bf16.h>
#include <cstdint>

// Problem dims
#define BB 8
#define SS 2048
#define DIN 1024
#define DOUT 64
#define ROWS_TOTAL (BB * SS)   // 16384
#define AP 72                  // padded bf16 row length (144 B) -> conflict-free ldmatrix

// Scratch for projected q/k/v (3 x 4 MB device globals; no allocs allowed)
__device__ float g_q[ROWS_TOTAL * DOUT];
__device__ float g_k[ROWS_TOTAL * DOUT];
__device__ float g_v[ROWS_TOTAL * DOUT];

// Pre-split, transposed weights: [w][kb][n][k_local] (kb = k/64)
__device__ __nv_bfloat16 g_Wh[3 * 16 * 64 * 64];
__device__ __nv_bfloat16 g_Wm[3 * 16 * 64 * 64];

// Mask dtype flag: 0 = uint8/bool, 1 = int32, 2 = float32
__device__ int g_mask_kind;

// ---------------------------------------------------------------------------
// helpers
// ---------------------------------------------------------------------------
static __device__ __forceinline__ uint32_t smem_u32(const void* p) {
    uint32_t a;
    asm("{ .reg .u64 t; cvta.to.shared.u64 t, %1; cvt.u32.u64 %0, t; }"
        : "=r"(a) : "l"(p));
    return a;
}
static __device__ __forceinline__ void ldsm_x4(uint32_t* r, uint32_t addr) {
    asm volatile("ldmatrix.sync.aligned.m8n8.x4.shared.b16 {%0,%1,%2,%3}, [%4];"
                 : "=r"(r[0]), "=r"(r[1]), "=r"(r[2]), "=r"(r[3]) : "r"(addr));
}
static __device__ __forceinline__ void ldsm_x2(uint32_t* r, uint32_t addr) {
    asm volatile("ldmatrix.sync.aligned.m8n8.x2.shared.b16 {%0,%1}, [%2];"
                 : "=r"(r[0]), "=r"(r[1]) : "r"(addr));
}
static __device__ __forceinline__ void mma16816(float* c, const uint32_t* a,
                                                const uint32_t* b) {
    asm volatile(
        "mma.sync.aligned.m16n8k16.row.col.f32.bf16.bf16.f32 "
        "{%0,%1,%2,%3}, {%4,%5,%6,%7}, {%8,%9}, {%0,%1,%2,%3};"
        : "+f"(c[0]), "+f"(c[1]), "+f"(c[2]), "+f"(c[3])
        : "r"(a[0]), "r"(a[1]), "r"(a[2]), "r"(a[3]), "r"(b[0]), "r"(b[1]));
}
static __device__ __forceinline__ void split2(float x, float y,
                                              uint32_t& hi, uint32_t& mid) {
    __nv_bfloat162 h = __floats2bfloat162_rn(x, y);
    __nv_bfloat162 m = __floats2bfloat162_rn(x - __bfloat162float(h.x),
                                             y - __bfloat162float(h.y));
    hi  = *(uint32_t*)&h;
    mid = *(uint32_t*)&m;
}
// fast 2^y on the FMA pipe; y <= 0 expected, clamped so exponent stays valid
static __device__ __forceinline__ float exp2_fast(float y) {
    y = fmaxf(y, -126.0f);
    float n = rintf(y);
    float f = y - n;                        // [-0.5, 0.5]
    float p = 1.3333558146428443e-3f;
    p = fmaf(p, f, 9.618129107628477e-3f);
    p = fmaf(p, f, 5.550410866482158e-2f);
    p = fmaf(p, f, 2.402265069591007e-1f);
    p = fmaf(p, f, 6.931471805599453e-1f);
    p = fmaf(p, f, 1.0f);
    float sc = __int_as_float(((int)n + 127) << 23);
    return p * sc;
}

// ---------------------------------------------------------------------------
// Kernel 0: sniff mask dtype (first 2048 words = 8 KB).
// ---------------------------------------------------------------------------
__global__ void detect_mask_kernel(const unsigned int* __restrict__ m)
{
    __shared__ int sawF, sawHigh;
    if (threadIdx.x == 0) { sawF = 0; sawHigh = 0; }
    __syncthreads();
    for (int i = threadIdx.x; i < 2048; i += 256) {
        unsigned int w = m[i];
        if (w == 0x3F800000u) sawF = 1;
        else if (w & 0xFFFFFF00u) sawHigh = 1;
    }
    __syncthreads();
    if (threadIdx.x == 0)
        g_mask_kind = sawF ? 2 : (sawHigh ? 0 : 1);
}

// ---------------------------------------------------------------------------
// Kernel P: split weights to bf16 hi/mid, transpose to [n][k] per K-block.
// ---------------------------------------------------------------------------
__global__ void prep_w_kernel(const float* __restrict__ Wq,
                              const float* __restrict__ Wk,
                              const float* __restrict__ Wv)
{
    int w = blockIdx.y;
    const float* W = (w == 0) ? Wq : (w == 1) ? Wk : Wv;
    int e = blockIdx.x * 256 + threadIdx.x;   // over [k][n]
    float x = W[e];
    int k = e >> 6, n = e & 63;
    __nv_bfloat16 hi = __float2bfloat16_rn(x);
    __nv_bfloat16 mid = __float2bfloat16_rn(x - __bfloat162float(hi));
    int o = w * 65536 + (k >> 6) * 4096 + n * 64 + (k & 63);
    g_Wh[o] = hi;
    g_Wm[o] = mid;
}

// ---------------------------------------------------------------------------
// Kernel 1: QKV projection via mma.sync bf16 3-MMA split (proven R6 version).
// ---------------------------------------------------------------------------
__global__ __launch_bounds__(256) void qkv_mma_kernel(
    const float* __restrict__ seq,
    const float* __restrict__ bq,
    const float* __restrict__ bk,
    const float* __restrict__ bv)
{
    extern __shared__ char smc[];
    __nv_bfloat16* Ah = (__nv_bfloat16*)smc;            // 128 x AP
    __nv_bfloat16* Am = Ah + 128 * AP;
    __nv_bfloat16* Bh = Am + 128 * AP;                  // 3 x 64 x AP
    __nv_bfloat16* Bm = Bh + 3 * 64 * AP;

    const int tid  = threadIdx.x;
    const int wid  = tid >> 5, lane = tid & 31;
    const int wm   = wid >> 1, wn = wid & 1;
    const int row0 = blockIdx.x * 128;
    const uint32_t sb  = smem_u32(smc);
    const uint32_t AhB = sb;
    const uint32_t AmB = sb + 128 * AP * 2;
    const uint32_t BhB = AmB + 128 * AP * 2;
    const uint32_t BmB = BhB + 3 * 64 * AP * 2;

    float cc[3][2][4][4];
#pragma unroll
    for (int w = 0; w < 3; w++)
#pragma unroll
        for (int mi = 0; mi < 2; mi++)
#pragma unroll
            for (int ni = 0; ni < 4; ni++)
#pragma unroll
                for (int r = 0; r < 4; r++) cc[w][mi][ni][r] = 0.0f;

    for (int kb = 0; kb < 16; kb++) {
        __syncthreads();
#pragma unroll
        for (int it = 0; it < 8; it++) {
            int f   = tid + it * 256;
            int row = f >> 4, k4 = f & 15;
            float4 t = *(const float4*)&seq[(size_t)(row0 + row) * DIN + kb * 64 + k4 * 4];
            uint32_t h0, m0, h1, m1;
            split2(t.x, t.y, h0, m0);
            split2(t.z, t.w, h1, m1);
            int off = row * AP + k4 * 4;
            *(uint32_t*)(Ah + off)     = h0;
            *(uint32_t*)(Ah + off + 2) = h1;
            *(uint32_t*)(Am + off)     = m0;
            *(uint32_t*)(Am + off + 2) = m1;
        }
        {
            const uint4* wh4 = (const uint4*)g_Wh;
            const uint4* wm4 = (const uint4*)g_Wm;
#pragma unroll
            for (int it = 0; it < 12; it++) {
                int u  = tid + it * 256;
                int sp = (u >= 1536);
                int u2 = u - sp * 1536;
                int w  = u2 >> 9;
                int r  = u2 & 511;
                int n  = r >> 3, ch = r & 7;
                uint4 val = (sp ? wm4 : wh4)[w * 8192 + kb * 512 + n * 8 + ch];
                __nv_bfloat16* dst = (sp ? Bm : Bh) + w * 64 * AP + n * AP + ch * 8;
                *(uint4*)dst = val;
            }
        }
        __syncthreads();

#pragma unroll
        for (int ks = 0; ks < 4; ks++) {
            const int k0 = ks * 16;
            uint32_t ah[2][4], am[2][4];
#pragma unroll
            for (int mi = 0; mi < 2; mi++) {
                uint32_t r = wm * 32 + mi * 16 + (lane & 15);
                uint32_t c = k0 + (lane >> 4) * 8;
                ldsm_x4(ah[mi], AhB + (r * AP + c) * 2);
                ldsm_x4(am[mi], AmB + (r * AP + c) * 2);
            }
#pragma unroll
            for (int w = 0; w < 3; w++) {
                const uint32_t base = w * 64 * AP * 2;
                uint32_t bh[4][2], bm[4][2];
#pragma unroll
                for (int ni = 0; ni < 4; ni++) {
                    uint32_t nr = wn * 32 + ni * 8 + (lane & 7);
                    uint32_t c  = k0 + ((lane >> 3) & 1) * 8;
                    ldsm_x2(bh[ni], BhB + base + (nr * AP + c) * 2);
                    ldsm_x2(bm[ni], BmB + base + (nr * AP + c) * 2);
                }
#pragma unroll
                for (int mi = 0; mi < 2; mi++)
#pragma unroll
                    for (int ni = 0; ni < 4; ni++) {
                        mma16816(cc[w][mi][ni], ah[mi], bh[ni]);
                        mma16816(cc[w][mi][ni], ah[mi], bm[ni]);
                        mma16816(cc[w][mi][ni], am[mi], bh[ni]);
                    }
            }
        }
    }

    const int g = lane >> 2, t4 = lane & 3;
#pragma unroll
    for (int w = 0; w < 3; w++) {
        const float* bias = (w == 0) ? bq : (w == 1) ? bk : bv;
        float* outp = (w == 0) ? g_q : (w == 1) ? g_k : g_v;
#pragma unroll
        for (int mi = 0; mi < 2; mi++)
#pragma unroll
            for (int ni = 0; ni < 4; ni++) {
                int row = row0 + wm * 32 + mi * 16 + g;
                int col = wn * 32 + ni * 8 + t4 * 2;
                float bx = bias[col], by = bias[col + 1];
                float2 r0 = make_float2(cc[w][mi][ni][0] + bx, cc[w][mi][ni][1] + by);
                float2 r1 = make_float2(cc[w][mi][ni][2] + bx, cc[w][mi][ni][3] + by);
                *(float2*)&outp[(size_t)row * 64 + col]       = r0;
                *(float2*)&outp[(size_t)(row + 8) * 64 + col] = r1;
            }
    }
}

// ---------------------------------------------------------------------------
// Kernel 2: register-resident flash-attention.
// CTA = (batch, 128-query tile), 8 warps, each warp owns 16 query rows.
// Q fragments in registers (loaded once); S, softmax, and P stay in registers
// (S C-fragment == PV A-fragment layout); exp on the FMA pipe.
// smem: mask[64] + union{ Q staging 128xAP hi/mid | Kh,Km,Vth,Vtm 64xAP }.
// ---------------------------------------------------------------------------
#define ASM_MF   0
#define ASM_BUF  256
#define ATTN_SMEM (ASM_BUF + 2 * 128 * AP * 2)   // 37120 B

__global__ __launch_bounds__(256) void attn_mma_kernel(
    const void* __restrict__ mask_raw,
    float* __restrict__ out)
{
    extern __shared__ char smc[];
    float* Mf = (float*)(smc + ASM_MF);
    char*  buf = smc + ASM_BUF;
    __nv_bfloat16* QSH = (__nv_bfloat16*)buf;          // 128 x AP
    __nv_bfloat16* QSM = QSH + 128 * AP;
    __nv_bfloat16* Kh  = (__nv_bfloat16*)buf;          // 64 x AP (overlaps QS)
    __nv_bfloat16* Km  = Kh + 64 * AP;
    __nv_bfloat16* Vth = Km + 64 * AP;
    __nv_bfloat16* Vtm = Vth + 64 * AP;
    const uint32_t sb = smem_u32(buf);

    const int b   = blockIdx.y;
    const int q0  = blockIdx.x * 128;
    const int tid = threadIdx.x;
    const int wq  = tid >> 5, lane = tid & 31;
    const int g   = lane >> 2, t4 = lane & 3;
    const float kscale = rsqrtf((float)SS) * 1.4426950408889634f;  // log2 domain
    const int   mask_kind = g_mask_kind;

    // ---- Q staging + fragment load (once) ----
#pragma unroll
    for (int it = 0; it < 8; it++) {
        int f   = tid + it * 256;
        int row = f >> 4, k4 = f & 15;
        float4 t = *(const float4*)&g_q[(size_t)(b * SS + q0 + row) * 64 + k4 * 4];
        uint32_t h0, m0, h1, m1;
        split2(t.x, t.y, h0, m0);
        split2(t.z, t.w, h1, m1);
        int off = row * AP + k4 * 4;
        *(uint32_t*)(QSH + off)     = h0;
        *(uint32_t*)(QSH + off + 2) = h1;
        *(uint32_t*)(QSM + off)     = m0;
        *(uint32_t*)(QSM + off + 2) = m1;
    }
    __syncthreads();
    uint32_t qh[4][4], qm[4][4];
#pragma unroll
    for (int ks = 0; ks < 4; ks++) {
        uint32_t r = wq * 16 + (lane & 15);
        uint32_t c = ks * 16 + (lane >> 4) * 8;
        ldsm_x4(qh[ks], sb + (r * AP + c) * 2);
        ldsm_x4(qm[ks], sb + (128 * AP + r * AP + c) * 2);
    }

    float ov[8][4];
#pragma unroll
    for (int ni = 0; ni < 8; ni++)
#pragma unroll
        for (int r = 0; r < 4; r++) ov[ni][r] = 0.0f;
    float mrun0 = -1e30f, mrun1 = -1e30f, lrun0 = 0.0f, lrun1 = 0.0f;

    const uint32_t lrb = (lane & 7) + ((lane >> 4) & 1) * 8;   // B-operand row within 16
    const int vd  = tid & 63;        // V-fill: d index
    const int vkg = tid >> 6;        // V-fill: key group (16 keys)

    for (int kt = 0; kt < 32; kt++) {
        const int kg = kt * 64;
        __syncthreads();   // protect K/V (and first-iter Q staging) from readers

        // K fill (64 x 64 -> hi/mid, row-major)
#pragma unroll
        for (int it = 0; it < 4; it++) {
            int f   = tid + it * 256;
            int row = f >> 4, k4 = f & 15;
            float4 t = *(const float4*)&g_k[(size_t)(b * SS + kg + row) * 64 + k4 * 4];
            uint32_t h0, m0, h1, m1;
            split2(t.x, t.y, h0, m0);
            split2(t.z, t.w, h1, m1);
            int off = row * AP + k4 * 4;
            *(uint32_t*)(Kh + off)     = h0;
            *(uint32_t*)(Kh + off + 2) = h1;
            *(uint32_t*)(Km + off)     = m0;
            *(uint32_t*)(Km + off + 2) = m1;
        }
        // V transposed fill: Vt[d][kk], coalesced loads, paired bf16x2 stores
#pragma unroll
        for (int kp = 0; kp < 8; kp++) {
            int kk = vkg * 16 + kp * 2;
            float a  = g_v[(size_t)(b * SS + kg + kk)     * 64 + vd];
            float bb = g_v[(size_t)(b * SS + kg + kk + 1) * 64 + vd];
            uint32_t h, mm;
            split2(a, bb, h, mm);
            *(uint32_t*)&Vth[vd * AP + kk] = h;
            *(uint32_t*)&Vtm[vd * AP + kk] = mm;
        }
        if (tid < 64) {
            int idx = b * SS + kg + tid;
            bool mk;
            if (mask_kind == 2)      mk = ((const float*)mask_raw)[idx] != 0.0f;
            else if (mask_kind == 1) mk = ((const int*)mask_raw)[idx] != 0;
            else                     mk = ((const unsigned char*)mask_raw)[idx] != 0;
            Mf[tid] = mk ? 1.0f : 0.0f;
        }
        __syncthreads();

        // ---- QK^T (3-MMA split), S in registers ----
        float sc[8][4];
#pragma unroll
        for (int ni = 0; ni < 8; ni++)
#pragma unroll
            for (int r = 0; r < 4; r++) sc[ni][r] = 0.0f;

#pragma unroll
        for (int ks = 0; ks < 4; ks++) {
            const uint32_t cc = ks * 16 + ((lane >> 3) & 1) * 8;
#pragma unroll
            for (int grp = 0; grp < 4; grp++) {
                uint32_t kh4[4], km4[4];
                uint32_t nr = grp * 16 + lrb;
                ldsm_x4(kh4, sb + (nr * AP + cc) * 2);
                ldsm_x4(km4, sb + (64 * AP + nr * AP + cc) * 2);
                mma16816(sc[grp * 2],     qh[ks], kh4);
                mma16816(sc[grp * 2],     qh[ks], km4);
                mma16816(sc[grp * 2],     qm[ks], kh4);
                mma16816(sc[grp * 2 + 1], qh[ks], kh4 + 2);
                mma16816(sc[grp * 2 + 1], qh[ks], km4 + 2);
                mma16816(sc[grp * 2 + 1], qm[ks], kh4 + 2);
            }
        }

        // ---- in-register online softmax (log2 domain) ----
        float rmax0 = -1e30f, rmax1 = -1e30f;
#pragma unroll
        for (int ni = 0; ni < 8; ni++) {
            float2 mf = *(float2*)&Mf[ni * 8 + t4 * 2];
            sc[ni][0] = (mf.x != 0.0f) ? -1e9f : sc[ni][0] * kscale;
            sc[ni][1] = (mf.y != 0.0f) ? -1e9f : sc[ni][1] * kscale;
            sc[ni][2] = (mf.x != 0.0f) ? -1e9f : sc[ni][2] * kscale;
            sc[ni][3] = (mf.y != 0.0f) ? -1e9f : sc[ni][3] * kscale;
            rmax0 = fmaxf(rmax0, fmaxf(sc[ni][0], sc[ni][1]));
            rmax1 = fmaxf(rmax1, fmaxf(sc[ni][2], sc[ni][3]));
        }
        rmax0 = fmaxf(rmax0, __shfl_xor_sync(0xffffffffu, rmax0, 1));
        rmax0 = fmaxf(rmax0, __shfl_xor_sync(0xffffffffu, rmax0, 2));
        rmax1 = fmaxf(rmax1, __shfl_xor_sync(0xffffffffu, rmax1, 1));
        rmax1 = fmaxf(rmax1, __shfl_xor_sync(0xffffffffu, rmax1, 2));
        float mn0 = fmaxf(mrun0, rmax0);
        float mn1 = fmaxf(mrun1, rmax1);
        float alpha0 = exp2_fast(mrun0 - mn0);
        float alpha1 = exp2_fast(mrun1 - mn1);
        mrun0 = mn0;
        mrun1 = mn1;
        float rs0 = 0.0f, rs1 = 0.0f;
#pragma unroll
        for (int ni = 0; ni < 8; ni++) {
            sc[ni][0] = exp2_fast(sc[ni][0] - mn0);
            sc[ni][1] = exp2_fast(sc[ni][1] - mn0);
            sc[ni][2] = exp2_fast(sc[ni][2] - mn1);
            sc[ni][3] = exp2_fast(sc[ni][3] - mn1);
            rs0 += sc[ni][0] + sc[ni][1];
            rs1 += sc[ni][2] + sc[ni][3];
        }
        rs0 += __shfl_xor_sync(0xffffffffu, rs0, 1);
        rs0 += __shfl_xor_sync(0xffffffffu, rs0, 2);
        rs1 += __shfl_xor_sync(0xffffffffu, rs1, 1);
        rs1 += __shfl_xor_sync(0xffffffffu, rs1, 2);
        lrun0 = lrun0 * alpha0 + rs0;
        lrun1 = lrun1 * alpha1 + rs1;

        // ---- rescale O, then PV (P packed from registers; V from smem) ----
#pragma unroll
        for (int ni = 0; ni < 8; ni++) {
            ov[ni][0] *= alpha0;
            ov[ni][1] *= alpha0;
            ov[ni][2] *= alpha1;
            ov[ni][3] *= alpha1;
        }
#pragma unroll
        for (int ks = 0; ks < 4; ks++) {
            uint32_t pah[4], pam[4];
            split2(sc[2 * ks][0],     sc[2 * ks][1],     pah[0], pam[0]);
            split2(sc[2 * ks][2],     sc[2 * ks][3],     pah[1], pam[1]);
            split2(sc[2 * ks + 1][0], sc[2 * ks + 1][1], pah[2], pam[2]);
            split2(sc[2 * ks + 1][2], sc[2 * ks + 1][3], pah[3], pam[3]);
            const uint32_t cc = ks * 16 + ((lane >> 3) & 1) * 8;
#pragma unroll
            for (int grp = 0; grp < 4; grp++) {
                uint32_t vh4[4], vm4[4];
                uint32_t nr = grp * 16 + lrb;
                ldsm_x4(vh4, sb + (2 * 64 * AP + nr * AP + cc) * 2);
                ldsm_x4(vm4, sb + (3 * 64 * AP + nr * AP + cc) * 2);
                mma16816(ov[grp * 2],     pah, vh4);
                mma16816(ov[grp * 2],     pah, vm4);
                mma16816(ov[grp * 2],     pam, vh4);
                mma16816(ov[grp * 2 + 1], pah, vh4 + 2);
                mma16816(ov[grp * 2 + 1], pah, vm4 + 2);
                mma16816(ov[grp * 2 + 1], pam, vh4 + 2);
            }
        }
    }

    // ---- final: divide by l, write out ----
    const float il0 = 1.0f / lrun0;
    const float il1 = 1.0f / lrun1;
    const int row = q0 + wq * 16 + g;
#pragma unroll
    for (int ni = 0; ni < 8; ni++) {
        int col = ni * 8 + t4 * 2;
        *(float2*)&out[((size_t)(b * SS) + row) * 64 + col] =
            make_float2(ov[ni][0] * il0, ov[ni][1] * il0);
        *(float2*)&out[((size_t)(b * SS) + row + 8) * 64 + col] =
            make_float2(ov[ni][2] * il1, ov[ni][3] * il1);
    }
}

// ---------------------------------------------------------------------------
extern "C" void kernel_launch(void* const* d_in, const int* in_sizes, int n_in,
                              void* d_out, int out_size)
{
    const float* seq  = (const float*)d_in[0];
    const void*  mask = d_in[1];
    const float* Wq   = (const float*)d_in[2];
    const float* bq   = (const float*)d_in[3];
    const float* Wk   = (const float*)d_in[4];
    const float* bk   = (const float*)d_in[5];
    const float* Wv   = (const float*)d_in[6];
    const float* bv   = (const float*)d_in[7];
    float* out = (float*)d_out;

    const int qkv_smem = (2 * 128 + 6 * 64) * AP * 2;   // 92160
    cudaFuncSetAttribute(qkv_mma_kernel,
                         cudaFuncAttributeMaxDynamicSharedMemorySize, qkv_smem);
    cudaFuncSetAttribute(attn_mma_kernel,
                         cudaFuncAttributeMaxDynamicSharedMemorySize, ATTN_SMEM);

    detect_mask_kernel<<<1, 256>>>((const unsigned int*)mask);
    prep_w_kernel<<<dim3(256, 3), 256>>>(Wq, Wk, Wv);
    qkv_mma_kernel<<<ROWS_TOTAL / 128, 256, qkv_smem>>>(seq, bq, bk, bv);
    attn_mma_kernel<<<dim3(SS / 128, BB), 256, ATTN_SMEM>>>(mask, out);
}